// round 4
// baseline (speedup 1.0000x reference)
#include <cuda_runtime.h>

// ---------------------------------------------------------------------------
// FFT long conv. Filter for (b,d) is b*32 + (d>>3); pack adjacent channel
// pairs (d,d+1) as z = u[...,d] + i*u[...,d+1] (contiguous float2 in u!).
//   w = IFFT( FFT(z) .* H_phi ),  Re->d, Im->d+1.  row r = b*128+(d>>1), phi=r>>2.
// Forward DIF, mul in digit-reversed order, inverse DIT. Fused global ends.
// All complex math uses sm_103a packed f32x2 ops (add/sub/mul/fma.rn.f32x2).
// ---------------------------------------------------------------------------

#define NFFT 16384
#define LSEQ 8192
#define KLEN 8192
#define DDIM 256
#define BATCH 8
#define CPAIR 128
#define NROWS (BATCH * CPAIR)     // 1024
#define START ((KLEN - 1) / 2)    // 4095
#define NTHREADS 512

#define PHYS(i) ((i) + ((i) >> 4))
#define SMEM_F2 (NFFT + (NFFT >> 4))
#define SMEM_BYTES (SMEM_F2 * (int)sizeof(unsigned long long))   // 139264 B

typedef unsigned long long cplx;   // packed (re, im) as f32x2

__device__ cplx g_Z[NROWS * LSEQ];   // packed input rows   (64 MB)
__device__ cplx g_W[NROWS * LSEQ];   // packed output rows  (64 MB)
__device__ cplx g_H[DDIM * NFFT];    // filter spectra, digit-reversed, /N  (32 MB)

// ---- packed f32x2 complex primitives --------------------------------------
__device__ __forceinline__ cplx cset(float x, float y) {
    cplx r; asm("mov.b64 %0, {%1, %2};" : "=l"(r) : "f"(x), "f"(y)); return r;
}
__device__ __forceinline__ float2 cget(cplx a) {
    float2 v; asm("mov.b64 {%0, %1}, %2;" : "=f"(v.x), "=f"(v.y) : "l"(a)); return v;
}
__device__ __forceinline__ cplx cadd(cplx a, cplx b) {
    cplx r; asm("add.rn.f32x2 %0, %1, %2;" : "=l"(r) : "l"(a), "l"(b)); return r;
}
__device__ __forceinline__ cplx csub(cplx a, cplx b) {
    cplx r; asm("sub.rn.f32x2 %0, %1, %2;" : "=l"(r) : "l"(a), "l"(b)); return r;
}
__device__ __forceinline__ cplx cmulp(cplx a, cplx b) {
    cplx r; asm("mul.rn.f32x2 %0, %1, %2;" : "=l"(r) : "l"(a), "l"(b)); return r;
}
__device__ __forceinline__ cplx cfma(cplx a, cplx b, cplx c) {
    cplx r; asm("fma.rn.f32x2 %0, %1, %2, %3;" : "=l"(r) : "l"(a), "l"(b), "l"(c)); return r;
}
__device__ __forceinline__ cplx crot_m(cplx v) {   // -i * v
    float2 f = cget(v); return cset(f.y, -f.x);
}
__device__ __forceinline__ cplx crot_p(cplx v) {   // +i * v
    float2 f = cget(v); return cset(-f.y, f.x);
}
// a * b, full complex product: 2 packed FMA-pipe ops
__device__ __forceinline__ cplx cmulf(cplx a, cplx b) {
    float2 av = cget(a);
    float2 bv = cget(b);
    cplx axx = cset(av.x, av.x);
    cplx ayy = cset(av.y, av.y);
    cplx bsw = cset(-bv.y, bv.x);
    return cfma(ayy, bsw, cmulp(axx, b));
}
// multiply by constant twiddle (c + i*DIR*s)
template<int DIR>
__device__ __forceinline__ cplx twc(cplx a, float c, float s) {
    const float si = (DIR < 0) ? -s : s;
    float2 av = cget(a);
    cplx axx = cset(av.x, av.x);
    cplx ayy = cset(av.y, av.y);
    return cfma(ayy, cset(-si, c), cmulp(axx, cset(c, si)));
}

template<int DIR>
__device__ __forceinline__ void dft4(cplx& a, cplx& b, cplx& c, cplx& d) {
    cplx t0 = cadd(a, c), t1 = csub(a, c);
    cplx t2 = cadd(b, d), t3 = csub(b, d);
    a = cadd(t0, t2);
    c = csub(t0, t2);
    cplx r = (DIR < 0) ? crot_m(t3) : crot_p(t3);
    b = cadd(t1, r);
    d = csub(t1, r);
}

// second layer of DFT16 (twiddles + row dft4s)
template<int DIR>
__device__ __forceinline__ void dft16_layer2(cplx v[16]) {
    const float C1 = 0.9238795325112867f, S1 = 0.3826834323650898f;
    const float R2 = 0.7071067811865476f;
    v[5]  = twc<DIR>(v[5],  C1,  S1);
    v[9]  = twc<DIR>(v[9],  R2,  R2);
    v[13] = twc<DIR>(v[13], S1,  C1);
    v[6]  = twc<DIR>(v[6],  R2,  R2);
    v[10] = (DIR < 0) ? crot_m(v[10]) : crot_p(v[10]);
    v[14] = twc<DIR>(v[14], -R2,  R2);
    v[7]  = twc<DIR>(v[7],   S1,  C1);
    v[11] = twc<DIR>(v[11], -R2,  R2);
    v[15] = twc<DIR>(v[15], -C1, -S1);
    dft4<DIR>(v[0],  v[1],  v[2],  v[3]);
    dft4<DIR>(v[4],  v[5],  v[6],  v[7]);
    dft4<DIR>(v[8],  v[9],  v[10], v[11]);
    dft4<DIR>(v[12], v[13], v[14], v[15]);
}

// Full DFT16. Output slot s = 4*(r&3)+(r>>2) holds spectral index r.
template<int DIR>
__device__ __forceinline__ void dft16(cplx v[16]) {
    dft4<DIR>(v[0], v[4], v[8],  v[12]);
    dft4<DIR>(v[1], v[5], v[9],  v[13]);
    dft4<DIR>(v[2], v[6], v[10], v[14]);
    dft4<DIR>(v[3], v[7], v[11], v[15]);
    dft16_layer2<DIR>(v);
}

// Forward DFT16 with inputs v[8..15] == 0 (zero-padded upper half).
__device__ __forceinline__ void dft16_fwd_hz(cplx v[16]) {
    #pragma unroll
    for (int k = 0; k < 4; k++) {
        cplx a = v[k], b = v[k + 4];
        cplx ibm = crot_m(b);             // -i*b
        v[k]      = cadd(a, b);
        v[k + 4]  = cadd(a, ibm);         // a - i b
        v[k + 8]  = csub(a, b);
        v[k + 12] = csub(a, ibm);         // a + i b
    }
    dft16_layer2<-1>(v);
}

// Generic mid radix-16 smem pass (used for M=1024 and M=64)
template<int DIR, int M>
__device__ __forceinline__ void radix16_stage(cplx* s, int tid) {
    constexpr int Ms = M >> 4;
    #pragma unroll
    for (int it = 0; it < (NFFT / 16) / NTHREADS; it++) {
        int g = tid + it * NTHREADS;
        int blk = (g / Ms) * M;
        int j   = g % Ms;
        int base = blk + j;
        float sv, cv;
        sincospif(2.0f * (float)j / (float)M, &sv, &cv);
        cplx w1 = cset(cv, (DIR < 0) ? -sv : sv);
        cplx v[16];
        if (DIR < 0) {
            #pragma unroll
            for (int m = 0; m < 16; m++) v[m] = s[PHYS(base + m * Ms)];
            dft16<DIR>(v);
            s[PHYS(base)] = v[0];
            cplx wr = w1;
            #pragma unroll
            for (int r = 1; r < 16; r++) {
                int sl = ((r & 3) << 2) | (r >> 2);
                s[PHYS(base + r * Ms)] = cmulf(v[sl], wr);
                wr = cmulf(wr, w1);
            }
        } else {
            v[0] = s[PHYS(base)];
            cplx wr = w1;
            #pragma unroll
            for (int r = 1; r < 16; r++) {
                v[r] = cmulf(s[PHYS(base + r * Ms)], wr);
                wr = cmulf(wr, w1);
            }
            dft16<DIR>(v);
            #pragma unroll
            for (int m = 0; m < 16; m++) {
                int sl = ((m & 3) << 2) | (m >> 2);
                s[PHYS(base + m * Ms)] = v[sl];
            }
        }
    }
    __syncthreads();
}

// Forward stage 1 (M=NFFT): load v[0..7] straight from global (upper half
// zero), half-zero DFT16, post-twiddle, store to smem.
__device__ __forceinline__ void fwd_stage1_global(const cplx* __restrict__ src,
                                                  cplx* s, int tid) {
    #pragma unroll
    for (int it = 0; it < (NFFT / 16) / NTHREADS; it++) {
        int j = tid + it * NTHREADS;
        cplx v[16];
        #pragma unroll
        for (int m = 0; m < 8; m++) v[m] = src[j + m * (NFFT / 16)];
        dft16_fwd_hz(v);
        float sv, cv;
        sincospif(2.0f * (float)j / (float)NFFT, &sv, &cv);
        cplx w1 = cset(cv, -sv);
        s[PHYS(j)] = v[0];
        cplx wr = w1;
        #pragma unroll
        for (int r = 1; r < 16; r++) {
            int sl = ((r & 3) << 2) | (r >> 2);
            s[PHYS(j + r * (NFFT / 16))] = cmulf(v[sl], wr);
            wr = cmulf(wr, w1);
        }
    }
    __syncthreads();
}

// Same for real input rows (h)
__device__ __forceinline__ void fwd_stage1_global_real(const float* __restrict__ src,
                                                       cplx* s, int tid) {
    #pragma unroll
    for (int it = 0; it < (NFFT / 16) / NTHREADS; it++) {
        int j = tid + it * NTHREADS;
        cplx v[16];
        #pragma unroll
        for (int m = 0; m < 8; m++) v[m] = cset(src[j + m * (NFFT / 16)], 0.f);
        dft16_fwd_hz(v);
        float sv, cv;
        sincospif(2.0f * (float)j / (float)NFFT, &sv, &cv);
        cplx w1 = cset(cv, -sv);
        s[PHYS(j)] = v[0];
        cplx wr = w1;
        #pragma unroll
        for (int r = 1; r < 16; r++) {
            int sl = ((r & 3) << 2) | (r >> 2);
            s[PHYS(j + r * (NFFT / 16))] = cmulf(v[sl], wr);
            wr = cmulf(wr, w1);
        }
    }
    __syncthreads();
}

// Fused: forward radix-4 (unit twiddle) -> ×H -> inverse radix-4, in registers.
__device__ __forceinline__ void fused_mul(cplx* s, const cplx* __restrict__ Hd, int tid) {
    #pragma unroll
    for (int it = 0; it < (NFFT / 4) / NTHREADS; it++) {
        int base = (tid + it * NTHREADS) * 4;
        cplx a = s[PHYS(base + 0)], b = s[PHYS(base + 1)];
        cplx c = s[PHYS(base + 2)], d = s[PHYS(base + 3)];
        dft4<-1>(a, b, c, d);
        ulonglong2 h01 = ((const ulonglong2*)Hd)[(base >> 1) + 0];
        ulonglong2 h23 = ((const ulonglong2*)Hd)[(base >> 1) + 1];
        a = cmulf(a, h01.x);
        b = cmulf(b, h01.y);
        c = cmulf(c, h23.x);
        d = cmulf(d, h23.y);
        dft4<1>(a, b, c, d);
        s[PHYS(base + 0)] = a; s[PHYS(base + 1)] = b;
        s[PHYS(base + 2)] = c; s[PHYS(base + 3)] = d;
    }
    __syncthreads();
}

// Inverse stage (M=NFFT): pre-twiddle, inverse DFT16, write window to global.
__device__ __forceinline__ void inv_stage_last_global(cplx* s, cplx* __restrict__ dst,
                                                      int tid) {
    #pragma unroll
    for (int it = 0; it < (NFFT / 16) / NTHREADS; it++) {
        int j = tid + it * NTHREADS;
        float sv, cv;
        sincospif(2.0f * (float)j / (float)NFFT, &sv, &cv);
        cplx w1 = cset(cv, sv);
        cplx v[16];
        v[0] = s[PHYS(j)];
        cplx wr = w1;
        #pragma unroll
        for (int r = 1; r < 16; r++) {
            v[r] = cmulf(s[PHYS(j + r * (NFFT / 16))], wr);
            wr = cmulf(wr, w1);
        }
        dft16<1>(v);
        #pragma unroll
        for (int m = 0; m < 16; m++) {
            int sl = ((m & 3) << 2) | (m >> 2);
            int l = j + m * (NFFT / 16) - START;
            if ((unsigned)l < (unsigned)LSEQ) dst[l] = v[sl];
        }
    }
}

// ---------------------------------------------------------------------------
// Kernel 1: per-batch float2 transpose.  u viewed as (B, L, 128) float2.
// ---------------------------------------------------------------------------
__global__ void __launch_bounds__(256) k_pack(const float* __restrict__ u) {
    __shared__ float2 tile[32][33];
    const int b  = blockIdx.z;
    const int c0 = blockIdx.y * 32;
    const int l0 = blockIdx.x * 32;
    const int tx = threadIdx.x, ty = threadIdx.y;
    const float2* __restrict__ u2 = (const float2*)u;
    #pragma unroll
    for (int i = 0; i < 4; i++) {
        int l = l0 + ty + 8 * i;
        tile[tx][ty + 8 * i] = u2[((size_t)b * LSEQ + l) * CPAIR + (c0 + tx)];
    }
    __syncthreads();
    #pragma unroll
    for (int i = 0; i < 4; i++) {
        int c = c0 + ty + 8 * i;
        int l = l0 + tx;
        float2 t = tile[ty + 8 * i][tx];
        g_Z[((size_t)b * CPAIR + c) * LSEQ + l] = cset(t.x, t.y);
    }
}

// ---------------------------------------------------------------------------
// Kernel 2: filter spectra, digit-reversed order, pre-scaled 1/N
// ---------------------------------------------------------------------------
__global__ void __launch_bounds__(NTHREADS, 1) k_hfft(const float* __restrict__ h) {
    extern __shared__ cplx s[];
    const int d = blockIdx.x, tid = threadIdx.x;
    fwd_stage1_global_real(h + (size_t)d * KLEN, s, tid);
    radix16_stage<-1, 1024>(s, tid);
    radix16_stage<-1, 64>(s, tid);
    const float inv = 1.0f / (float)NFFT;
    const cplx vinv = cset(inv, inv);
    cplx* __restrict__ Hd = g_H + (size_t)d * NFFT;
    #pragma unroll
    for (int it = 0; it < (NFFT / 4) / NTHREADS; it++) {
        int base = (tid + it * NTHREADS) * 4;
        cplx a = s[PHYS(base + 0)], b = s[PHYS(base + 1)];
        cplx c = s[PHYS(base + 2)], e = s[PHYS(base + 3)];
        dft4<-1>(a, b, c, e);
        Hd[base + 0] = cmulp(a, vinv);
        Hd[base + 1] = cmulp(b, vinv);
        Hd[base + 2] = cmulp(c, vinv);
        Hd[base + 3] = cmulp(e, vinv);
    }
}

// ---------------------------------------------------------------------------
// Kernel 3: per packed row: FFT -> .*H -> IFFT -> window -> g_W
// ---------------------------------------------------------------------------
__global__ void __launch_bounds__(NTHREADS, 1) k_conv() {
    extern __shared__ cplx s[];
    const int row = blockIdx.x;
    const int phi = row >> 2;
    const int tid = threadIdx.x;
    fwd_stage1_global(g_Z + (size_t)row * LSEQ, s, tid);
    radix16_stage<-1, 1024>(s, tid);
    radix16_stage<-1, 64>(s, tid);
    fused_mul(s, g_H + (size_t)phi * NFFT, tid);
    radix16_stage<1, 64>(s, tid);
    radix16_stage<1, 1024>(s, tid);
    inv_stage_last_global(s, g_W + (size_t)row * LSEQ, tid);
}

// ---------------------------------------------------------------------------
// Kernel 4: per-batch float2 transpose back.
// ---------------------------------------------------------------------------
__global__ void __launch_bounds__(256) k_unpack(float* __restrict__ y) {
    __shared__ float2 tile[32][33];
    const int b  = blockIdx.z;
    const int c0 = blockIdx.y * 32;
    const int l0 = blockIdx.x * 32;
    const int tx = threadIdx.x, ty = threadIdx.y;
    float2* __restrict__ y2 = (float2*)y;
    #pragma unroll
    for (int i = 0; i < 4; i++) {
        int c = c0 + ty + 8 * i;
        int l = l0 + tx;
        tile[ty + 8 * i][tx] = cget(g_W[((size_t)b * CPAIR + c) * LSEQ + l]);
    }
    __syncthreads();
    #pragma unroll
    for (int i = 0; i < 4; i++) {
        int l = l0 + ty + 8 * i;
        y2[((size_t)b * LSEQ + l) * CPAIR + (c0 + tx)] = tile[tx][ty + 8 * i];
    }
}

// ---------------------------------------------------------------------------
extern "C" void kernel_launch(void* const* d_in, const int* in_sizes, int n_in,
                              void* d_out, int out_size) {
    (void)in_sizes; (void)n_in; (void)out_size;
    const float* u = (const float*)d_in[0];
    const float* h = (const float*)d_in[1];
    float* y = (float*)d_out;

    cudaFuncSetAttribute(k_hfft, cudaFuncAttributeMaxDynamicSharedMemorySize, SMEM_BYTES);
    cudaFuncSetAttribute(k_conv, cudaFuncAttributeMaxDynamicSharedMemorySize, SMEM_BYTES);

    dim3 tb(32, 8);
    dim3 tg(LSEQ / 32, CPAIR / 32, BATCH);

    k_pack<<<tg, tb>>>(u);
    k_hfft<<<DDIM, NTHREADS, SMEM_BYTES>>>(h);
    k_conv<<<NROWS, NTHREADS, SMEM_BYTES>>>();
    k_unpack<<<tg, tb>>>(y);
}